// round 8
// baseline (speedup 1.0000x reference)
#include <cuda_runtime.h>

#define NN 10000
#define EE 640000           // == 625 * 256 * 4 exactly
#define TRI_N 49995000      // N*(N-1)/2
#define NEG_SLOPE 0.01f
#define SCAN_T 1024
#define CHUNK 10            // ceil(NN / SCAN_T)

// ---------------------------------------------------------------------------
// Scratch (device globals; BSS zero-initialized at load, so g_cnt/g_agg start 0)
// ---------------------------------------------------------------------------
__device__ int    g_cnt[NN];       // per-target running counters
__device__ int    g_row[NN + 1];   // CSR row pointers
__device__ float4 g_edge[EE];      // CSR edges: (ef0, ef1, ef2, pack(src | tgt<<14))
__device__ float4 g_agg[NN];       // per-layer aggregation (atomic per component)
__device__ float4 g_xa[NN];        // x ping (padded to 16B for 1-load gather)
__device__ float4 g_xb[NN];        // x pong

// ---------------------------------------------------------------------------
// 1) Histogram of targets (4 edges/thread via 2x int4) + node_embeds -> float4
//    + zero g_agg.
// ---------------------------------------------------------------------------
__global__ void __launch_bounds__(256) hist_kernel(const int* __restrict__ edge_index,
                                                   const float* __restrict__ node_embeds) {
    int t = blockIdx.x * blockDim.x + threadIdx.x;   // 0 .. EE/4-1 (160000)

    if (t < NN) {
        const float* p = node_embeds + 3 * t;
        g_xa[t]  = make_float4(p[0], p[1], p[2], 0.0f);
        g_agg[t] = make_float4(0.0f, 0.0f, 0.0f, 0.0f);
    }

    if (4 * t >= EE) return;
    int4 q0 = ((const int4*)edge_index)[2 * t];      // edges 4t, 4t+1
    int4 q1 = ((const int4*)edge_index)[2 * t + 1];  // edges 4t+2, 4t+3
    atomicAdd(&g_cnt[q0.y], 1);
    atomicAdd(&g_cnt[q0.w], 1);
    atomicAdd(&g_cnt[q1.y], 1);
    atomicAdd(&g_cnt[q1.w], 1);
}

// ---------------------------------------------------------------------------
// 2) Exclusive prefix scan over the 10k counters -> g_row; zero counters
// ---------------------------------------------------------------------------
__global__ void scan_kernel() {
    __shared__ int sp[SCAN_T];
    int tid = threadIdx.x;
    int beg = tid * CHUNK;
    int end = min(beg + CHUNK, NN);

    int local[CHUNK];
    int sum = 0;
    for (int k = beg; k < end; k++) {
        int v = g_cnt[k];
        local[k - beg] = v;
        sum += v;
    }
    sp[tid] = sum;
    __syncthreads();

    for (int off = 1; off < SCAN_T; off <<= 1) {
        int v = (tid >= off) ? sp[tid - off] : 0;
        __syncthreads();
        sp[tid] += v;
        __syncthreads();
    }

    int run = (tid == 0) ? 0 : sp[tid - 1];  // exclusive
    for (int k = beg; k < end; k++) {
        g_row[k] = run;
        run += local[k - beg];
        g_cnt[k] = 0;                        // ready for scatter
    }
    if (tid == 0) g_row[NN] = EE;
}

// ---------------------------------------------------------------------------
// 3) Scatter: 4 edges/thread. All 12 random feature loads issued before any
//    dependent atomic/store -> MLP 12 against the 600MB gather.
// ---------------------------------------------------------------------------
__global__ void __launch_bounds__(256) scatter_kernel(const float* __restrict__ edge_embeds,
                                                      const int* __restrict__ edge_index) {
    int t = blockIdx.x * blockDim.x + threadIdx.x;   // 0 .. EE/4-1
    if (4 * t >= EE) return;

    int4 q0 = ((const int4*)edge_index)[2 * t];
    int4 q1 = ((const int4*)edge_index)[2 * t + 1];
    int sx[4] = { q0.x, q0.z, q1.x, q1.z };
    int tx[4] = { q0.y, q0.w, q1.y, q1.w };

    long long tri[4];
#pragma unroll
    for (int i = 0; i < 4; i++) {
        int a = min(sx[i], tx[i]), b = max(sx[i], tx[i]);
        int tr = a * NN - (a * (a + 3)) / 2 + b - 1;
        if (tr < 0) tr += TRI_N;             // JAX wraps index -1 (a==b==0)
        tri[i] = (long long)tr * 3;
    }

    float f0[4], f1[4], f2[4];
#pragma unroll
    for (int i = 0; i < 4; i++) {            // 12 independent loads in flight
        const float* p = edge_embeds + tri[i];
        f0[i] = __ldg(p + 0);
        f1[i] = __ldg(p + 1);
        f2[i] = __ldg(p + 2);
    }

#pragma unroll
    for (int i = 0; i < 4; i++) {
        int pos = g_row[tx[i]] + atomicAdd(&g_cnt[tx[i]], 1);
        int pk = sx[i] | (tx[i] << 14);      // both < 2^14
        __stcg(&g_edge[pos], make_float4(f0[i], f1[i], f2[i], __int_as_float(pk)));
    }
}

// ---------------------------------------------------------------------------
// 4a) Edge pass (per layer): each warp handles 4 consecutive 32-edge windows.
//     All 8 loads (4 edge float4 + 4 x float4) issue before the shuffle phase.
//     Segmented warp suffix-reduction per window, then spread atomics.
// ---------------------------------------------------------------------------
__global__ void __launch_bounds__(256) edge_kernel(int in_sel) {
    int wg   = (blockIdx.x * blockDim.x + threadIdx.x) >> 5;  // global warp id
    int lane = threadIdx.x & 31;
    int base = wg * 128;                     // 4 windows of 32 edges

    const float4* __restrict__ x = in_sel ? g_xb : g_xa;

    float4 v[4];
#pragma unroll
    for (int c = 0; c < 4; c++)
        v[c] = __ldg(&g_edge[base + c * 32 + lane]);

    float4 xs[4];
#pragma unroll
    for (int c = 0; c < 4; c++)
        xs[c] = __ldg(&x[__float_as_int(v[c].w) & 0x3FFF]);

#pragma unroll
    for (int c = 0; c < 4; c++) {
        int t = __float_as_int(v[c].w) >> 14;
        float m0 = fmaxf(xs[c].x + v[c].x, 0.0f);
        float m1 = fmaxf(xs[c].y + v[c].y, 0.0f);
        float m2 = fmaxf(xs[c].z + v[c].z, 0.0f);

        // Segmented suffix reduction (t non-decreasing within the window)
#pragma unroll
        for (int off = 1; off < 32; off <<= 1) {
            float b0 = __shfl_down_sync(0xFFFFFFFF, m0, off);
            float b1 = __shfl_down_sync(0xFFFFFFFF, m1, off);
            float b2 = __shfl_down_sync(0xFFFFFFFF, m2, off);
            int   tn = __shfl_down_sync(0xFFFFFFFF, t,  off);
            if (lane + off < 32 && tn == t) { m0 += b0; m1 += b1; m2 += b2; }
        }
        int tp = __shfl_up_sync(0xFFFFFFFF, t, 1);
        if (lane == 0 || tp != t) {
            float* agg = (float*)&g_agg[t];
            atomicAdd(agg + 0, m0);
            atomicAdd(agg + 1, m1);
            atomicAdd(agg + 2, m2);
        }
    }
}

// ---------------------------------------------------------------------------
// 4b) Node pass (per layer): one thread per node, full-ILP MLP.
//     Re-zeros g_agg for the next layer / replay; layer 0 re-zeros g_cnt.
// ---------------------------------------------------------------------------
__device__ __forceinline__ float leaky(float v) {
    return v >= 0.0f ? v : NEG_SLOPE * v;
}

__global__ void __launch_bounds__(256) node_kernel(
                             int in_sel, int out_sel,
                             float* __restrict__ d_out,
                             const float* __restrict__ W1, const float* __restrict__ b1,
                             const float* __restrict__ W2, const float* __restrict__ b2,
                             const float* __restrict__ W3, const float* __restrict__ b3,
                             const float* __restrict__ W4, const float* __restrict__ b4,
                             int layer) {
    __shared__ float sW1[36], sb1[6], sW2[36], sb2[6], sW3[18], sb3[3], sW4[9], sb4[3];
    int tid = threadIdx.x;
    if (tid < 36) { sW1[tid] = W1[layer * 36 + tid]; sW2[tid] = W2[layer * 36 + tid]; }
    if (tid < 18) { sW3[tid] = W3[layer * 18 + tid]; }
    if (tid < 9)  { sW4[tid] = W4[layer * 9 + tid]; }
    if (tid < 6)  { sb1[tid] = b1[layer * 6 + tid]; sb2[tid] = b2[layer * 6 + tid]; }
    if (tid < 3)  { sb3[tid] = b3[layer * 3 + tid]; sb4[tid] = b4[layer * 3 + tid]; }
    __syncthreads();

    int i = blockIdx.x * blockDim.x + tid;
    if (i >= NN) return;

    const float4* __restrict__ x = in_sel ? g_xb : g_xa;

    float4 ag = g_agg[i];
    g_agg[i] = make_float4(0.0f, 0.0f, 0.0f, 0.0f);   // ready for next layer/replay
    if (layer == 0) g_cnt[i] = 0;                     // ready for next replay

    float4 xi = x[i];
    float h[6];
    h[0] = ag.x; h[1] = ag.y; h[2] = ag.z;
    h[3] = xi.x; h[4] = xi.y; h[5] = xi.z;

    float t1[6], t2[6], t3[3];
#pragma unroll
    for (int j = 0; j < 6; j++) {
        float acc = sb1[j];
#pragma unroll
        for (int k = 0; k < 6; k++) acc = fmaf(h[k], sW1[k * 6 + j], acc);
        t1[j] = leaky(acc);
    }
#pragma unroll
    for (int j = 0; j < 6; j++) {
        float acc = sb2[j];
#pragma unroll
        for (int k = 0; k < 6; k++) acc = fmaf(t1[k], sW2[k * 6 + j], acc);
        t2[j] = leaky(acc);
    }
#pragma unroll
    for (int j = 0; j < 3; j++) {
        float acc = sb3[j];
#pragma unroll
        for (int k = 0; k < 6; k++) acc = fmaf(t2[k], sW3[k * 3 + j], acc);
        t3[j] = leaky(acc);
    }
    float o0 = sb4[0], o1 = sb4[1], o2 = sb4[2];
#pragma unroll
    for (int k = 0; k < 3; k++) {
        o0 = fmaf(t3[k], sW4[k * 3 + 0], o0);
        o1 = fmaf(t3[k], sW4[k * 3 + 1], o1);
        o2 = fmaf(t3[k], sW4[k * 3 + 2], o2);
    }

    if (out_sel == 2) {                  // final layer -> packed N x 3 output
        d_out[3 * i + 0] = o0;
        d_out[3 * i + 1] = o1;
        d_out[3 * i + 2] = o2;
    } else {
        float4* xo = out_sel ? g_xb : g_xa;
        xo[i] = make_float4(o0, o1, o2, 0.0f);
    }
}

// ---------------------------------------------------------------------------
// kernel_launch
// ---------------------------------------------------------------------------
extern "C" void kernel_launch(void* const* d_in, const int* in_sizes, int n_in,
                              void* d_out, int out_size) {
    const float* node_embeds = (const float*)d_in[0];
    const float* edge_embeds = (const float*)d_in[1];
    const int*   edge_index  = (const int*)d_in[2];
    const float* W1 = (const float*)d_in[3];
    const float* b1 = (const float*)d_in[4];
    const float* W2 = (const float*)d_in[5];
    const float* b2 = (const float*)d_in[6];
    const float* W3 = (const float*)d_in[7];
    const float* b3 = (const float*)d_in[8];
    const float* W4 = (const float*)d_in[9];
    const float* b4 = (const float*)d_in[10];
    float* out = (float*)d_out;

    const int EB = 256;
    const int qgrid = EE / 4 / EB;               // 625 (4 edges/thread; covers NN conv)
    const int egrid = EE / 4 / EB;               // 625 (128 edges/warp)
    const int ngrid = (NN + EB - 1) / EB;        // 40

    hist_kernel<<<qgrid, EB>>>(edge_index, node_embeds);
    scan_kernel<<<1, SCAN_T>>>();
    scatter_kernel<<<qgrid, EB>>>(edge_embeds, edge_index);

    // layer 0: g_xa -> g_xb ; layer 1: g_xb -> g_xa ; layer 2: g_xa -> d_out
    edge_kernel<<<egrid, EB>>>(0);
    node_kernel<<<ngrid, EB>>>(0, 1, out, W1, b1, W2, b2, W3, b3, W4, b4, 0);
    edge_kernel<<<egrid, EB>>>(1);
    node_kernel<<<ngrid, EB>>>(1, 0, out, W1, b1, W2, b2, W3, b3, W4, b4, 1);
    edge_kernel<<<egrid, EB>>>(0);
    node_kernel<<<ngrid, EB>>>(0, 2, out, W1, b1, W2, b2, W3, b3, W4, b4, 2);
}

// round 9
// speedup vs baseline: 1.0833x; 1.0833x over previous
#include <cuda_runtime.h>

#define NN 10000
#define EE 640000           // == 2500 * 256 exactly (edge kernel has no ragged tail)
#define TRI_N 49995000      // N*(N-1)/2
#define NEG_SLOPE 0.01f
#define SCAN_T 1024
#define CHUNK 10            // ceil(NN / SCAN_T)

// ---------------------------------------------------------------------------
// Scratch (device globals; BSS zero-initialized at load, so g_cnt/g_agg start 0)
// ---------------------------------------------------------------------------
__device__ int    g_cnt[NN];       // per-target running counters
__device__ int    g_row[NN + 1];   // CSR row pointers
__device__ float4 g_edge[EE];      // CSR edges: (ef0, ef1, ef2, pack(src | tgt<<14))
__device__ float4 g_agg[NN];       // per-layer aggregation (atomic per component)
__device__ float4 g_xa[NN];        // x ping (padded to 16B for 1-load gather)
__device__ float4 g_xb[NN];        // x pong

// ---------------------------------------------------------------------------
// 1) Histogram of targets (2 edges/thread via int4) + node_embeds -> float4
//    + zero g_agg.
// ---------------------------------------------------------------------------
__global__ void __launch_bounds__(256) hist_kernel(const int* __restrict__ edge_index,
                                                   const float* __restrict__ node_embeds) {
    int t = blockIdx.x * blockDim.x + threadIdx.x;

    if (t < NN) {
        const float* p = node_embeds + 3 * t;
        g_xa[t]  = make_float4(p[0], p[1], p[2], 0.0f);
        g_agg[t] = make_float4(0.0f, 0.0f, 0.0f, 0.0f);
    }

    if (2 * t >= EE) return;
    int4 q = ((const int4*)edge_index)[t];   // edges 2t and 2t+1
    atomicAdd(&g_cnt[q.y], 1);
    atomicAdd(&g_cnt[q.w], 1);
}

// ---------------------------------------------------------------------------
// 2) Exclusive prefix scan over the 10k counters -> g_row; zero counters
// ---------------------------------------------------------------------------
__global__ void scan_kernel() {
    __shared__ int sp[SCAN_T];
    int tid = threadIdx.x;
    int beg = tid * CHUNK;
    int end = min(beg + CHUNK, NN);

    int local[CHUNK];
    int sum = 0;
    for (int k = beg; k < end; k++) {
        int v = g_cnt[k];
        local[k - beg] = v;
        sum += v;
    }
    sp[tid] = sum;
    __syncthreads();

    for (int off = 1; off < SCAN_T; off <<= 1) {
        int v = (tid >= off) ? sp[tid - off] : 0;
        __syncthreads();
        sp[tid] += v;
        __syncthreads();
    }

    int run = (tid == 0) ? 0 : sp[tid - 1];  // exclusive
    for (int k = beg; k < end; k++) {
        g_row[k] = run;
        run += local[k - beg];
        g_cnt[k] = 0;                        // ready for scatter
    }
    if (tid == 0) g_row[NN] = EE;
}

// ---------------------------------------------------------------------------
// 3) Scatter: 2 edges/thread. Random gather from the 600MB triangular array
//    with __ldcs (one-shot streaming: don't evict g_edge from L2). Plain
//    stores for g_edge so it STAYS L2-resident for the 3 edge passes.
// ---------------------------------------------------------------------------
__global__ void __launch_bounds__(256) scatter_kernel(const float* __restrict__ edge_embeds,
                                                      const int* __restrict__ edge_index) {
    int t = blockIdx.x * blockDim.x + threadIdx.x;
    if (2 * t >= EE) return;

    int4 q = ((const int4*)edge_index)[t];
    int sA = q.x, tA = q.y;
    int sB = q.z, tB = q.w;

    int aA = min(sA, tA), bA = max(sA, tA);
    int aB = min(sB, tB), bB = max(sB, tB);
    int triA = aA * NN - (aA * (aA + 3)) / 2 + bA - 1;
    int triB = aB * NN - (aB * (aB + 3)) / 2 + bB - 1;
    if (triA < 0) triA += TRI_N;             // JAX wraps index -1 (a==b==0)
    if (triB < 0) triB += TRI_N;

    const float* pA = edge_embeds + (long long)triA * 3;
    const float* pB = edge_embeds + (long long)triB * 3;
    // 6 independent streaming loads in flight
    float fA0 = __ldcs(pA + 0), fA1 = __ldcs(pA + 1), fA2 = __ldcs(pA + 2);
    float fB0 = __ldcs(pB + 0), fB1 = __ldcs(pB + 1), fB2 = __ldcs(pB + 2);

    int posA = g_row[tA] + atomicAdd(&g_cnt[tA], 1);
    int posB = g_row[tB] + atomicAdd(&g_cnt[tB], 1);
    int pkA = sA | (tA << 14);               // both < 2^14
    int pkB = sB | (tB << 14);
    g_edge[posA] = make_float4(fA0, fA1, fA2, __int_as_float(pkA));
    g_edge[posB] = make_float4(fB0, fB1, fB2, __int_as_float(pkB));
}

// ---------------------------------------------------------------------------
// 4a) Edge pass (per layer): one thread per edge. msg = relu(x[src]+ef),
//     segmented warp suffix-reduction over the sorted tgt runs, then one
//     global atomicAdd per (segment-head, component).
// ---------------------------------------------------------------------------
__global__ void __launch_bounds__(256) edge_kernel(int in_sel) {
    int e = blockIdx.x * blockDim.x + threadIdx.x;   // EE is a multiple of 256
    int lane = threadIdx.x & 31;

    const float4* __restrict__ x = in_sel ? g_xb : g_xa;

    float4 v = __ldg(&g_edge[e]);
    int pk = __float_as_int(v.w);
    int s = pk & 0x3FFF;
    int t = pk >> 14;

    float4 xs = __ldg(&x[s]);
    float m0 = fmaxf(xs.x + v.x, 0.0f);
    float m1 = fmaxf(xs.y + v.y, 0.0f);
    float m2 = fmaxf(xs.z + v.z, 0.0f);

    // Segmented suffix reduction: after this, each segment-head lane holds
    // the sum of its run (t is non-decreasing within the warp).
#pragma unroll
    for (int off = 1; off < 32; off <<= 1) {
        float b0 = __shfl_down_sync(0xFFFFFFFF, m0, off);
        float b1 = __shfl_down_sync(0xFFFFFFFF, m1, off);
        float b2 = __shfl_down_sync(0xFFFFFFFF, m2, off);
        int   tn = __shfl_down_sync(0xFFFFFFFF, t,  off);
        if (lane + off < 32 && tn == t) { m0 += b0; m1 += b1; m2 += b2; }
    }
    int tp = __shfl_up_sync(0xFFFFFFFF, t, 1);
    if (lane == 0 || tp != t) {
        float* agg = (float*)&g_agg[t];
        atomicAdd(agg + 0, m0);
        atomicAdd(agg + 1, m1);
        atomicAdd(agg + 2, m2);
    }
}

// ---------------------------------------------------------------------------
// 4b) Node pass (per layer): one thread per node, full-ILP MLP.
//     Re-zeros g_agg for the next layer / replay; layer 0 re-zeros g_cnt.
// ---------------------------------------------------------------------------
__device__ __forceinline__ float leaky(float v) {
    return v >= 0.0f ? v : NEG_SLOPE * v;
}

__global__ void __launch_bounds__(256) node_kernel(
                             int in_sel, int out_sel,
                             float* __restrict__ d_out,
                             const float* __restrict__ W1, const float* __restrict__ b1,
                             const float* __restrict__ W2, const float* __restrict__ b2,
                             const float* __restrict__ W3, const float* __restrict__ b3,
                             const float* __restrict__ W4, const float* __restrict__ b4,
                             int layer) {
    __shared__ float sW1[36], sb1[6], sW2[36], sb2[6], sW3[18], sb3[3], sW4[9], sb4[3];
    int tid = threadIdx.x;
    if (tid < 36) { sW1[tid] = W1[layer * 36 + tid]; sW2[tid] = W2[layer * 36 + tid]; }
    if (tid < 18) { sW3[tid] = W3[layer * 18 + tid]; }
    if (tid < 9)  { sW4[tid] = W4[layer * 9 + tid]; }
    if (tid < 6)  { sb1[tid] = b1[layer * 6 + tid]; sb2[tid] = b2[layer * 6 + tid]; }
    if (tid < 3)  { sb3[tid] = b3[layer * 3 + tid]; sb4[tid] = b4[layer * 3 + tid]; }
    __syncthreads();

    int i = blockIdx.x * blockDim.x + tid;
    if (i >= NN) return;

    const float4* __restrict__ x = in_sel ? g_xb : g_xa;

    float4 ag = g_agg[i];
    g_agg[i] = make_float4(0.0f, 0.0f, 0.0f, 0.0f);   // ready for next layer/replay
    if (layer == 0) g_cnt[i] = 0;                     // ready for next replay

    float4 xi = x[i];
    float h[6];
    h[0] = ag.x; h[1] = ag.y; h[2] = ag.z;
    h[3] = xi.x; h[4] = xi.y; h[5] = xi.z;

    float t1[6], t2[6], t3[3];
#pragma unroll
    for (int j = 0; j < 6; j++) {
        float acc = sb1[j];
#pragma unroll
        for (int k = 0; k < 6; k++) acc = fmaf(h[k], sW1[k * 6 + j], acc);
        t1[j] = leaky(acc);
    }
#pragma unroll
    for (int j = 0; j < 6; j++) {
        float acc = sb2[j];
#pragma unroll
        for (int k = 0; k < 6; k++) acc = fmaf(t1[k], sW2[k * 6 + j], acc);
        t2[j] = leaky(acc);
    }
#pragma unroll
    for (int j = 0; j < 3; j++) {
        float acc = sb3[j];
#pragma unroll
        for (int k = 0; k < 6; k++) acc = fmaf(t2[k], sW3[k * 3 + j], acc);
        t3[j] = leaky(acc);
    }
    float o0 = sb4[0], o1 = sb4[1], o2 = sb4[2];
#pragma unroll
    for (int k = 0; k < 3; k++) {
        o0 = fmaf(t3[k], sW4[k * 3 + 0], o0);
        o1 = fmaf(t3[k], sW4[k * 3 + 1], o1);
        o2 = fmaf(t3[k], sW4[k * 3 + 2], o2);
    }

    if (out_sel == 2) {                  // final layer -> packed N x 3 output
        d_out[3 * i + 0] = o0;
        d_out[3 * i + 1] = o1;
        d_out[3 * i + 2] = o2;
    } else {
        float4* xo = out_sel ? g_xb : g_xa;
        xo[i] = make_float4(o0, o1, o2, 0.0f);
    }
}

// ---------------------------------------------------------------------------
// kernel_launch
// ---------------------------------------------------------------------------
extern "C" void kernel_launch(void* const* d_in, const int* in_sizes, int n_in,
                              void* d_out, int out_size) {
    const float* node_embeds = (const float*)d_in[0];
    const float* edge_embeds = (const float*)d_in[1];
    const int*   edge_index  = (const int*)d_in[2];
    const float* W1 = (const float*)d_in[3];
    const float* b1 = (const float*)d_in[4];
    const float* W2 = (const float*)d_in[5];
    const float* b2 = (const float*)d_in[6];
    const float* W3 = (const float*)d_in[7];
    const float* b3 = (const float*)d_in[8];
    const float* W4 = (const float*)d_in[9];
    const float* b4 = (const float*)d_in[10];
    float* out = (float*)d_out;

    const int EB = 256;
    const int hgrid = (EE / 2 + EB - 1) / EB;    // 2 edges/thread (covers NN too)
    const int egrid = EE / EB;                   // exact: 2500
    const int ngrid = (NN + EB - 1) / EB;        // 40

    hist_kernel<<<hgrid, EB>>>(edge_index, node_embeds);
    scan_kernel<<<1, SCAN_T>>>();
    scatter_kernel<<<hgrid, EB>>>(edge_embeds, edge_index);

    // layer 0: g_xa -> g_xb ; layer 1: g_xb -> g_xa ; layer 2: g_xa -> d_out
    edge_kernel<<<egrid, EB>>>(0);
    node_kernel<<<ngrid, EB>>>(0, 1, out, W1, b1, W2, b2, W3, b3, W4, b4, 0);
    edge_kernel<<<egrid, EB>>>(1);
    node_kernel<<<ngrid, EB>>>(1, 0, out, W1, b1, W2, b2, W3, b3, W4, b4, 1);
    edge_kernel<<<egrid, EB>>>(0);
    node_kernel<<<ngrid, EB>>>(0, 2, out, W1, b1, W2, b2, W3, b3, W4, b4, 2);
}